// round 10
// baseline (speedup 1.0000x reference)
#include <cuda_runtime.h>
#include <math.h>

#define BB   512
#define MM   32
#define NAG  8
#define HH   256
#define KH   128          // K half
#define NACT 16
#define HO   (HH * NAG)   // 2048

#define ACT_OFF  0
#define BASE_OFF 8192
#define HID_OFF  8704
#define COMM_OFF 139776

__device__ float g_csum[BB * HH];
__device__ float g_part[2 * BB * HH];    // hid partials: one slab per matrix
__device__ int   g_cnt[MM];
__device__ int   g_list[MM * BB];

__global__ void k_zero() {
    if (threadIdx.x < MM) g_cnt[threadIdx.x] = 0;
}

// Per-example agent-sum + model-id grouping lists
__global__ void k_prep(const float* __restrict__ comm_in,
                       const int* __restrict__ mid) {
    int b = blockIdx.x;
    int h = threadIdx.x;
    const float* p = comm_in + b * NAG * HH + h;
    float s = 0.f;
#pragma unroll
    for (int a = 0; a < NAG; a++) s += p[a * HH];
    g_csum[b * HH + h] = s;
    if (h == 0) {
        int m = mid[b];
        int slot = atomicAdd(&g_cnt[m], 1);
        g_list[m * BB + slot] = b;
    }
}

// hid partial GEMM per matrix, K-split 2-way combined in smem.
// grid (32, mat*2 + coltile), 256 threads = (khalf 2) x (128 cols).
__global__ void __launch_bounds__(256) k_hidmm(
                      const float* __restrict__ prev_hid,
                      const float* __restrict__ Wc,
                      const float* __restrict__ Wr) {
    int m = blockIdx.x;
    int n = g_cnt[m];
    if (n == 0) return;
    int mat = blockIdx.y >> 1;
    int tc  = threadIdx.x & 127;
    int kh  = threadIdx.x >> 7;
    int col = (blockIdx.y & 1) * 128 + tc;

    const float* W = (mat ? Wr : Wc) + m * HH * HH + kh * KH * HH + col;
    const float* X = (mat ? prev_hid : g_csum);
    float* P = g_part + mat * (BB * HH);

    __shared__ float xs[8][HH];
    __shared__ float cbuf[8][128];
    __shared__ int   rows[8];

    for (int base = 0; base < n; base += 8) {
        int R = n - base; if (R > 8) R = 8;
        for (int i = threadIdx.x; i < 8 * HH; i += 256) {
            int r = i >> 8;
            int k = i & (HH - 1);
            int rr  = (r < R) ? r : 0;
            int row = g_list[m * BB + base + rr];
            xs[r][k] = X[row * HH + k];
            if (k == 0) rows[r] = row;
        }
        __syncthreads();

        float acc[8];
#pragma unroll
        for (int r = 0; r < 8; r++) acc[r] = 0.f;

        for (int k = 0; k < KH; k += 8) {
            float w[8];
#pragma unroll
            for (int u = 0; u < 8; u++) w[u] = W[(k + u) * HH];
#pragma unroll
            for (int u = 0; u < 8; u++) {
#pragma unroll
                for (int r = 0; r < 8; r++) acc[r] += xs[r][kh * KH + k + u] * w[u];
            }
        }

        if (kh == 0) {
#pragma unroll
            for (int r = 0; r < 8; r++) cbuf[r][tc] = acc[r];
        }
        __syncthreads();
        if (kh == 1) {
            for (int r = 0; r < R; r++)
                P[rows[r] * HH + col] = acc[r] + cbuf[r][tc];
        }
        __syncthreads();
    }
}

// Fused: hid = tanh(partC + partR + biases + lut); action softmax + baseline.
__global__ void __launch_bounds__(128) k_hidact(
                      const int* __restrict__ mid,
                      const float* __restrict__ bc, const float* __restrict__ br,
                      const float* __restrict__ lut, const int* __restrict__ inp,
                      const float* __restrict__ enc_bias,
                      const float* __restrict__ Wa, const float* __restrict__ ba,
                      const float* __restrict__ Wb, const float* __restrict__ bb,
                      float* __restrict__ hid,
                      float* __restrict__ act, float* __restrict__ base_out) {
    int b = blockIdx.x;
    int t = threadIdx.x;
    int m = mid[b];

    __shared__ float hsh[HH];
    __shared__ float sps[32 * 16];   // [kc][a] partials
    __shared__ float sb[4];

#pragma unroll
    for (int c = t; c < HH; c += 128) {
        float v = g_part[b * HH + c] + g_part[BB * HH + b * HH + c]
                + bc[m * HH + c] + br[m * HH + c]
                + enc_bias[c] + lut[inp[b] * HH + c];
        float h = tanhf(v);
        hid[b * HH + c] = h;
        hsh[c] = h;
    }
    __syncthreads();

    // action partials: aq = t&3 (4 actions each), kc = t>>2 (8 k's each); float4 Wa loads
    {
        int aq = t & 3;
        int kc = t >> 2;
        const float4* WaP = (const float4*)(Wa + m * HH * NACT + aq * 4);
        float4 a4 = make_float4(0.f, 0.f, 0.f, 0.f);
#pragma unroll
        for (int j = 0; j < 8; j++) {
            int k = kc * 8 + j;
            float4 w = WaP[k * 4];
            float x = hsh[k];
            a4.x += x * w.x; a4.y += x * w.y; a4.z += x * w.z; a4.w += x * w.w;
        }
        *(float4*)&sps[kc * 16 + aq * 4] = a4;
    }
    // baseline partial
    {
        const float* WbP = Wb + m * HH;
        float pv = hsh[t] * WbP[t] + hsh[t + 128] * WbP[t + 128];
#pragma unroll
        for (int o = 16; o > 0; o >>= 1) pv += __shfl_xor_sync(0xffffffffu, pv, o);
        if ((t & 31) == 0) sb[t >> 5] = pv;
    }
    __syncthreads();

    if (t < NACT) {
        float v = ba[m * NACT + t];
#pragma unroll
        for (int kc = 0; kc < 32; kc++) v += sps[kc * 16 + t];
        float mx = v;
#pragma unroll
        for (int o = 8; o > 0; o >>= 1) mx = fmaxf(mx, __shfl_xor_sync(0xffffu, mx, o, 16));
        float ev = expf(v - mx);
        float sum = ev;
#pragma unroll
        for (int o = 8; o > 0; o >>= 1) sum += __shfl_xor_sync(0xffffu, sum, o, 16);
        act[b * NACT + t] = ev / sum;
    }
    if (t == 0) base_out[b] = sb[0] + sb[1] + sb[2] + sb[3] + bb[m];
}

// comm_out GEMM, K-split 2-way combined in smem, direct store (no partials).
// grid (32, 8 col-tiles of 256), 256 threads = (khalf 2) x (128 cols), float2/thread.
__global__ void __launch_bounds__(256) k_commout(
                          const float* __restrict__ hid,
                          const float* __restrict__ Wo,
                          const float* __restrict__ bo,
                          float* __restrict__ comm) {
    int m = blockIdx.x;
    int n = g_cnt[m];
    if (n == 0) return;
    int tc   = threadIdx.x & 127;
    int kh   = threadIdx.x >> 7;
    int col0 = blockIdx.y * 256 + tc * 2;

    __shared__ float  hs[8][HH];
    __shared__ float2 cbuf[8][128];
    __shared__ int    rows[8];

    const float2* WoP = (const float2*)(Wo + (size_t)m * HH * HO + (size_t)kh * KH * HO + col0);
    float2 bov = *(const float2*)(bo + m * HO + col0);

    for (int base = 0; base < n; base += 8) {
        int R = n - base; if (R > 8) R = 8;
        for (int i = threadIdx.x; i < 8 * HH; i += 256) {
            int r = i >> 8;
            int k = i & (HH - 1);
            int rr  = (r < R) ? r : 0;
            int row = g_list[m * BB + base + rr];
            hs[r][k] = hid[row * HH + k];
            if (k == 0) rows[r] = row;
        }
        __syncthreads();

        float2 acc[8];
#pragma unroll
        for (int r = 0; r < 8; r++) { acc[r].x = 0.f; acc[r].y = 0.f; }

        for (int k = 0; k < KH; k += 8) {
            float2 w[8];
#pragma unroll
            for (int u = 0; u < 8; u++) w[u] = WoP[(k + u) * (HO / 2)];
#pragma unroll
            for (int u = 0; u < 8; u++) {
#pragma unroll
                for (int r = 0; r < 8; r++) {
                    float x = hs[r][kh * KH + k + u];
                    acc[r].x += x * w[u].x;
                    acc[r].y += x * w[u].y;
                }
            }
        }

        if (kh == 0) {
#pragma unroll
            for (int r = 0; r < 8; r++) cbuf[r][tc] = acc[r];
        }
        __syncthreads();
        if (kh == 1) {
            for (int r = 0; r < R; r++) {
                int row = rows[r];
                float2 c0 = cbuf[r][tc];
                float2 o;
                o.x = (acc[r].x + c0.x + bov.x) * (1.0f / 7.0f);
                o.y = (acc[r].y + c0.y + bov.y) * (1.0f / 7.0f);
                *(float2*)(comm + (size_t)row * HO + col0) = o;
            }
        }
        __syncthreads();
    }
}

extern "C" void kernel_launch(void* const* d_in, const int* in_sizes, int n_in,
                              void* d_out, int out_size) {
    const float* comm_in  = (const float*)d_in[0];
    const int*   inp      = (const int*)d_in[1];
    const float* prev_hid = (const float*)d_in[2];
    const int*   mid      = (const int*)d_in[4];
    const float* Wc       = (const float*)d_in[5];
    const float* bc       = (const float*)d_in[6];
    const float* Wr       = (const float*)d_in[7];
    const float* br       = (const float*)d_in[8];
    const float* Wa       = (const float*)d_in[9];
    const float* ba       = (const float*)d_in[10];
    const float* Wb       = (const float*)d_in[11];
    const float* bb       = (const float*)d_in[12];
    const float* Wo       = (const float*)d_in[13];
    const float* bo       = (const float*)d_in[14];
    const float* lut      = (const float*)d_in[15];
    const float* enc_bias = (const float*)d_in[16];

    float* out  = (float*)d_out;
    float* act  = out + ACT_OFF;
    float* base = out + BASE_OFF;
    float* hid  = out + HID_OFF;
    float* comm = out + COMM_OFF;

    k_zero<<<1, 32>>>();
    k_prep<<<BB, HH>>>(comm_in, mid);
    k_hidmm<<<dim3(MM, 4), 256>>>(prev_hid, Wc, Wr);
    k_hidact<<<BB, 128>>>(mid, bc, br, lut, inp, enc_bias,
                          Wa, ba, Wb, bb, hid, act, base);
    k_commout<<<dim3(MM, 8), 256>>>(hid, Wo, bo, comm);
}